// round 13
// baseline (speedup 1.0000x reference)
#include <cuda_runtime.h>

#define DIM 1024
#define NQ 10
#define NL 4
#define WPB 4                          // warps per block (each warp = 2 rows)
#define SWP(i) ((i) + ((i) >> 5))      // stride-33 swizzle, conflict-free both ways

typedef unsigned long long u64;

// Fused path (g[0]): stages 0-4 fast-Givens {-T, T, unused}; stages 5-9 full
// rotation {C, S, -S} (stage 5 scaled by prod of fast-stage scales).
// General path: per-layer full rotations {C, S, -S}.
struct Blob {
    int npasses;
    int ident;
    int mlo;        // bits of stages 0-4 that used cot-form (deferred swap+sign)
    int pad;
    u64 g[NL][NQ][3];
};

__device__ Blob g_blob;
__device__ int  g_perm[DIM];

__device__ __forceinline__ u64 pk2(float lo, float hi) {
    u64 r; asm("mov.b64 %0, {%1, %2};" : "=l"(r) : "f"(lo), "f"(hi)); return r;
}
__device__ __forceinline__ void unpk2(u64 v, float& lo, float& hi) {
    asm("mov.b64 {%0, %1}, %2;" : "=f"(lo), "=f"(hi) : "l"(v));
}
__device__ __forceinline__ u64 fma2(u64 a, u64 b, u64 c) {
    u64 d; asm("fma.rn.f32x2 %0, %1, %2, %3;" : "=l"(d) : "l"(a), "l"(b), "l"(c)); return d;
}
__device__ __forceinline__ u64 mul2(u64 a, u64 b) {
    u64 d; asm("mul.rn.f32x2 %0, %1, %2;" : "=l"(d) : "l"(a), "l"(b)); return d;
}
// volatile LDS.64 broadcast: pinned in place (no hoist into registers),
// no global memory-clobber -> FMA scheduling around it stays free.
__device__ __forceinline__ u64 lds64v(const u64* p) {
    u64 v;
    asm volatile("ld.shared.b64 %0, [%1];"
                 : "=l"(v) : "r"((unsigned)__cvta_generic_to_shared(p)));
    return v;
}

// ---------------------------------------------------------------------------
// Prep: perm via diagonal shortcut, identity flag, per-bit rotation angles.
// Fused (identity) path: per-bit angle = sum over layers; stages 0-4 emitted
// as fast-Givens (tan-form if |tan|<=1, else cot-form with deferred swap+sign
// recorded in mlo); accumulated scale folded into stage-5 coefficients.
// ---------------------------------------------------------------------------
__global__ void prep_kernel(const float* __restrict__ C,
                            const float* __restrict__ angles) {
    __shared__ int s_ident;
    __shared__ float TH[NL][NQ];      // per (layer, bit) rotation angle
    __shared__ float THS[NQ];         // fused per-bit angle (sum over layers)
    int tid = threadIdx.x;
    if (tid == 0) s_ident = 1;
    __syncthreads();

    // permutation-matrix row i: perm[i]=i iff C[i][i] != 0
    {
        int p = tid;
        float d = C[(size_t)tid * DIM + tid];
        if (d == 0.0f) {
            atomicExch(&s_ident, 0);
            const float* row = C + (size_t)tid * DIM;
            for (int j = 0; j < DIM; j++)
                if (row[j] != 0.0f) { p = j; break; }
        }
        g_perm[tid] = p;
    }

    // gate (l,q) = R(a2/2)R(a1/2)R(a0/2) = rotation by (a0+a1+a2)/2
    if (tid < NL * NQ) {
        int l = tid / NQ, q = tid % NQ, b = 9 - q;   // bit index b
        const float* a = angles + (size_t)(l * NQ + q) * 3;
        TH[l][b] = 0.5f * (a[0] + a[1] + a[2]);
    }
    __syncthreads();

    if (s_ident) {
        if (tid < NQ) {
            float th = 0.f;
            #pragma unroll
            for (int l = 0; l < NL; l++) th += TH[l][tid];
            THS[tid] = th;
        }
        __syncthreads();
        if (tid < NQ) {
            int b = tid;
            float th = THS[b];
            if (b < 5) {
                // fast-Givens: coefficient = tan or -cot, |coef| <= 1 always
                float t = tanf(th);
                float T = (fabsf(t) <= 1.0f) ? t : (-1.0f / t);
                g_blob.g[0][b][0] = pk2(-T, -T);
                g_blob.g[0][b][1] = pk2(T, T);
                g_blob.g[0][b][2] = 0;
            } else {
                float c = cosf(th), s = sinf(th);
                if (b == 5) {   // fold the accumulated fast-stage scale here
                    float K = 1.0f;
                    #pragma unroll
                    for (int bb = 0; bb < 5; bb++) {
                        float tb = THS[bb];
                        K *= (fabsf(tanf(tb)) <= 1.0f) ? cosf(tb) : sinf(tb);
                    }
                    c *= K; s *= K;
                }
                g_blob.g[0][b][0] = pk2(c, c);
                g_blob.g[0][b][1] = pk2(s, s);
                g_blob.g[0][b][2] = pk2(-s, -s);
            }
        }
        if (tid == 0) {
            int m = 0;
            #pragma unroll
            for (int bb = 0; bb < 5; bb++)
                if (fabsf(tanf(THS[bb])) > 1.0f) m |= 1 << bb;
            g_blob.mlo = m;
            g_blob.npasses = 1; g_blob.ident = 1;
        }
    } else {
        if (tid < NL * NQ) {
            int l = tid / NQ, b = tid % NQ;
            float th = TH[l][b];
            float c = cosf(th), s = sinf(th);
            g_blob.g[l][b][0] = pk2(c, c);
            g_blob.g[l][b][1] = pk2(s, s);
            g_blob.g[l][b][2] = pk2(-s, -s);
        }
        if (tid == 0) { g_blob.npasses = NL; g_blob.ident = 0; g_blob.mlo = 0; }
    }
}

// ---------------------------------------------------------------------------
// Main: one warp per TWO rows, f32x2 packed butterflies (rows in the lanes).
// Fused path: stages 0-4 are 2-op fast-Givens; deferred cot swaps fold into
// the transpose-read lane index (lane^mlo) and a per-thread sign XOR; stages
// 5-9 full rotation form (stage 5 carries the scale).
// STORE: stage the row pair in smem in exact global layout (conflict-free
// STS.32), then ONE cp.async.bulk (TMA pipe) per warp -- removes 64 STG.32
// of LSU issue cost per warp.
// ---------------------------------------------------------------------------
__global__ __launch_bounds__(32 * WPB)
void qnet_kernel(const float* __restrict__ x, float* __restrict__ out, int nrows) {
    __shared__ __align__(16) u64 buf[WPB][DIM + DIM / 32];   // 8448 B/warp
    __shared__ u64 scoef[NL][NQ][3];
    __shared__ unsigned short sperm[DIM + DIM / 32];   // general path only

    int tid = threadIdx.x;
    int4 hdr = *(const int4*)&g_blob.npasses;          // {npasses, ident, mlo, pad}
    int np = hdr.x;
    bool fused = (np == 1) && hdr.y;
    int mlo = hdr.z;

    if (tid < NL * NQ * 3)
        ((u64*)scoef)[tid] = ((const u64*)g_blob.g)[tid];
    if (!fused) {
        for (int i = tid; i < DIM; i += blockDim.x)
            sperm[SWP(i)] = (unsigned short)SWP(g_perm[i]);
    }
    __syncthreads();

    int warp = tid >> 5, lane = tid & 31;
    int pairi = blockIdx.x * WPB + warp;
    int row0 = pairi * 2;
    if (row0 >= nrows) return;
    int row1 = (row0 + 1 < nrows) ? row0 + 1 : row0;
    u64* wb = buf[warp];

    // ---- load both rows, layout A, pack {row0, row1} into f32x2 ----
    u64 r[32];
    {
        const float4* p0 = (const float4*)(x + (size_t)row0 * DIM + lane * 32);
        const float4* p1 = (const float4*)(x + (size_t)row1 * DIM + lane * 32);
        #pragma unroll
        for (int k4 = 0; k4 < 8; k4++) {
            float4 v0 = p0[k4], v1 = p1[k4];
            r[k4 * 4 + 0] = pk2(v0.x, v1.x);
            r[k4 * 4 + 1] = pk2(v0.y, v1.y);
            r[k4 * 4 + 2] = pk2(v0.z, v1.z);
            r[k4 * 4 + 3] = pk2(v0.w, v1.w);
        }
    }

    if (fused) {
        // ---- stages 0..4: fast-Givens, 2 ops per butterfly ----
        #pragma unroll
        for (int b = 0; b < 5; b++) {
            const u64* gg = scoef[0][b];
            u64 gN = lds64v(gg + 0);   // -T
            u64 gT = lds64v(gg + 1);   //  T
            int m = 1 << b;
            #pragma unroll
            for (int k0 = 0; k0 < 32; k0++) {
                if (k0 & m) continue;
                int k1 = k0 | m;
                u64 x0 = r[k0], x1 = r[k1];
                r[k0] = fma2(gN, x1, x0);
                r[k1] = fma2(gT, x0, x1);
            }
        }

        // ---- transpose A -> B; deferred cot swaps fold into read lane ----
        __syncwarp();
        #pragma unroll
        for (int k = 0; k < 32; k++) wb[SWP(lane * 32 + k)] = r[k];
        __syncwarp();
        int laneX = lane ^ mlo;
        #pragma unroll
        for (int k = 0; k < 32; k++) r[k] = wb[SWP(k * 32 + laneX)];

        // ---- deferred cot sign: per-thread constant XOR ----
        if (mlo) {
            u64 lsgn = (__popc(laneX & mlo) & 1) ? 0x8000000080000000ULL : 0ULL;
            #pragma unroll
            for (int k = 0; k < 32; k++) r[k] ^= lsgn;
        }

        // ---- stages 5..9: full rotation form (stage 5 carries scale K) ----
        #pragma unroll
        for (int b = 5; b < 10; b++) {
            const u64* gg = scoef[0][b];
            u64 gC = lds64v(gg + 0), gS = lds64v(gg + 1), gN = lds64v(gg + 2);
            int m = 1 << (b - 5);
            #pragma unroll
            for (int k0 = 0; k0 < 32; k0++) {
                if (k0 & m) continue;
                int k1 = k0 | m;
                u64 x0 = r[k0], x1 = r[k1];
                r[k0] = fma2(gC, x0, mul2(gN, x1));
                r[k1] = fma2(gS, x0, mul2(gC, x1));
            }
        }

        // ---- store: stage pair in smem in exact global layout, then one
        //      bulk async copy (TMA pipe) for the whole 8 KB row pair ----
        __syncwarp();
        float* sb = (float*)wb;                       // 8448 B >= 8192 B
        #pragma unroll
        for (int k = 0; k < 32; k++) {
            float lo, hi; unpk2(r[k], lo, hi);
            sb[k * 32 + lane]        = lo;            // row0: [0, 4096)
            sb[1024 + k * 32 + lane] = hi;            // row1: [4096, 8192)
        }
        __syncwarp();
        asm volatile("fence.proxy.async.shared::cta;" ::: "memory");
        if (lane == 0) {
            unsigned saddr = (unsigned)__cvta_generic_to_shared(sb);
            int nbytes = (row1 != row0) ? 2 * DIM * 4 : DIM * 4;
            asm volatile(
                "cp.async.bulk.global.shared::cta.bulk_group [%0], [%1], %2;"
                :: "l"(out + (size_t)row0 * DIM), "r"(saddr), "r"(nbytes)
                : "memory");
            asm volatile("cp.async.bulk.commit_group;" ::: "memory");
            asm volatile("cp.async.bulk.wait_group 0;" ::: "memory");
        }
        return;
    }

    // =================== general path (multi-pass, permutation) ===========
    for (int p = 0; p < np; p++) {
        #pragma unroll
        for (int b = 0; b < 5; b++) {
            const u64* gg = scoef[p][b];
            u64 gC = lds64v(gg + 0), gS = lds64v(gg + 1), gN = lds64v(gg + 2);
            int m = 1 << b;
            #pragma unroll
            for (int k0 = 0; k0 < 32; k0++) {
                if (k0 & m) continue;
                int k1 = k0 | m;
                u64 x0 = r[k0], x1 = r[k1];
                r[k0] = fma2(gC, x0, mul2(gN, x1));
                r[k1] = fma2(gS, x0, mul2(gC, x1));
            }
        }

        __syncwarp();
        #pragma unroll
        for (int k = 0; k < 32; k++) wb[SWP(lane * 32 + k)] = r[k];
        __syncwarp();
        #pragma unroll
        for (int k = 0; k < 32; k++) r[k] = wb[SWP(k * 32 + lane)];

        #pragma unroll
        for (int b = 5; b < 10; b++) {
            const u64* gg = scoef[p][b];
            u64 gC = lds64v(gg + 0), gS = lds64v(gg + 1), gN = lds64v(gg + 2);
            int m = 1 << (b - 5);
            #pragma unroll
            for (int k0 = 0; k0 < 32; k0++) {
                if (k0 & m) continue;
                int k1 = k0 | m;
                u64 x0 = r[k0], x1 = r[k1];
                r[k0] = fma2(gC, x0, mul2(gN, x1));
                r[k1] = fma2(gS, x0, mul2(gC, x1));
            }
        }

        // transpose B -> A with perm folded into the gather
        __syncwarp();
        #pragma unroll
        for (int k = 0; k < 32; k++) wb[SWP(k * 32 + lane)] = r[k];
        __syncwarp();
        #pragma unroll
        for (int k = 0; k < 32; k++) r[k] = wb[sperm[SWP(lane * 32 + k)]];
    }

    // store layout A: 8x STG.128 per row
    float4* o0 = (float4*)(out + (size_t)row0 * DIM + lane * 32);
    float4* o1 = (float4*)(out + (size_t)row1 * DIM + lane * 32);
    #pragma unroll
    for (int k4 = 0; k4 < 8; k4++) {
        float4 v0, v1;
        unpk2(r[k4 * 4 + 0], v0.x, v1.x);
        unpk2(r[k4 * 4 + 1], v0.y, v1.y);
        unpk2(r[k4 * 4 + 2], v0.z, v1.z);
        unpk2(r[k4 * 4 + 3], v0.w, v1.w);
        o0[k4] = v0; o1[k4] = v1;
    }
}

// ---------------------------------------------------------------------------
extern "C" void kernel_launch(void* const* d_in, const int* in_sizes, int n_in,
                              void* d_out, int out_size) {
    const float* x      = (const float*)d_in[0];   // [BATCH, 1024]
    const float* angles = (const float*)d_in[1];   // [4, 10, 3]
    const float* cnot   = (const float*)d_in[2];   // [1024, 1024]
    float* out = (float*)d_out;

    int nrows = in_sizes[0] / DIM;

    prep_kernel<<<1, DIM>>>(cnot, angles);

    int npairs  = (nrows + 1) / 2;
    int nblocks = (npairs + WPB - 1) / WPB;
    qnet_kernel<<<nblocks, 32 * WPB>>>(x, out, nrows);
}

// round 14
// speedup vs baseline: 1.1877x; 1.1877x over previous
#include <cuda_runtime.h>

#define DIM 1024
#define NQ 10
#define NL 4
#define WPB 4                          // warps per block (each warp = 2 rows)
#define SWP(i) ((i) + ((i) >> 5))      // stride-33 swizzle for transpose scratch

typedef unsigned long long u64;

struct Blob {
    int npasses;
    int ident;
    u64 g[NL][NQ][3];   // packed f32x2 {v,v}: [pass][bit][C, S, -S]
};

__device__ Blob g_blob;
__device__ int  g_perm[DIM];

__device__ __forceinline__ u64 pk2(float lo, float hi) {
    u64 r; asm("mov.b64 %0, {%1, %2};" : "=l"(r) : "f"(lo), "f"(hi)); return r;
}
__device__ __forceinline__ void unpk2(u64 v, float& lo, float& hi) {
    asm("mov.b64 {%0, %1}, %2;" : "=f"(lo), "=f"(hi) : "l"(v));
}
__device__ __forceinline__ u64 fma2(u64 a, u64 b, u64 c) {
    u64 d; asm("fma.rn.f32x2 %0, %1, %2, %3;" : "=l"(d) : "l"(a), "l"(b), "l"(c)); return d;
}
__device__ __forceinline__ u64 mul2(u64 a, u64 b) {
    u64 d; asm("mul.rn.f32x2 %0, %1, %2;" : "=l"(d) : "l"(a), "l"(b)); return d;
}
// volatile LDS.64 broadcast: pinned in place (no register hoisting),
// no global memory-clobber -> FMA scheduling around it stays free.
__device__ __forceinline__ u64 lds64v(const u64* p) {
    u64 v;
    asm volatile("ld.shared.b64 %0, [%1];"
                 : "=l"(v) : "r"((unsigned)__cvta_generic_to_shared(p)));
    return v;
}

// ---------------------------------------------------------------------------
// Prep: perm via diagonal shortcut, identity flag, per-bit rotation angles
// (gate = rotation by (a0+a1+a2)/2; 4->1 layer composition = angle sum when
// perm is identity). One block, 1024 threads.
// ---------------------------------------------------------------------------
__global__ void prep_kernel(const float* __restrict__ C,
                            const float* __restrict__ angles) {
    __shared__ int s_ident;
    __shared__ float TH[NL][NQ];
    int tid = threadIdx.x;
    if (tid == 0) s_ident = 1;
    __syncthreads();

    {   // permutation-matrix row i: perm[i]=i iff C[i][i] != 0
        int p = tid;
        float d = C[(size_t)tid * DIM + tid];
        if (d == 0.0f) {
            atomicExch(&s_ident, 0);
            const float* row = C + (size_t)tid * DIM;
            for (int j = 0; j < DIM; j++)
                if (row[j] != 0.0f) { p = j; break; }
        }
        g_perm[tid] = p;
    }

    if (tid < NL * NQ) {
        int l = tid / NQ, q = tid % NQ, b = 9 - q;
        const float* a = angles + (size_t)(l * NQ + q) * 3;
        TH[l][b] = 0.5f * (a[0] + a[1] + a[2]);
    }
    __syncthreads();

    if (s_ident) {
        if (tid < NQ) {
            int b = tid;
            float th = 0.f;
            #pragma unroll
            for (int l = 0; l < NL; l++) th += TH[l][b];
            float c = cosf(th), s = sinf(th);
            g_blob.g[0][b][0] = pk2(c, c);
            g_blob.g[0][b][1] = pk2(s, s);
            g_blob.g[0][b][2] = pk2(-s, -s);
        }
        if (tid == 0) { g_blob.npasses = 1; g_blob.ident = 1; }
    } else {
        if (tid < NL * NQ) {
            int l = tid / NQ, b = tid % NQ;
            float th = TH[l][b];
            float c = cosf(th), s = sinf(th);
            g_blob.g[l][b][0] = pk2(c, c);
            g_blob.g[l][b][1] = pk2(s, s);
            g_blob.g[l][b][2] = pk2(-s, -s);
        }
        if (tid == 0) { g_blob.npasses = NL; g_blob.ident = 0; }
    }
}

// 16B-chunk XOR swizzle for the cp.async landing buffer: chunk c of a row
// lands at c ^ ((c>>3)&7). Reader (lane l, chunk j of 8): c' = l*8 + (j^(l&7))
// -> conflict-free LDS.128; writer lanes are conflict-free likewise.
__device__ __forceinline__ void issue_pair_copy(
    const float* __restrict__ x, int row0, int nrows, unsigned land, int lane) {
    #pragma unroll
    for (int i = 0; i < 16; i++) {
        int ct = i * 32 + lane;           // 512 chunks of 16 B = 2 rows
        int r  = ct >> 8;
        int c  = ct & 255;
        int cs = c ^ ((c >> 3) & 7);
        int srow = row0 + r;
        if (srow >= nrows) srow = row0;   // odd tail: duplicate row0
        const float* src = x + (size_t)srow * DIM + c * 4;
        unsigned dst = land + r * 4096 + cs * 16;
        asm volatile("cp.async.cg.shared.global [%0], [%1], 16;"
                     :: "r"(dst), "l"(src) : "memory");
    }
    asm volatile("cp.async.commit_group;" ::: "memory");
}

// ---------------------------------------------------------------------------
// Main: grid-stride over row pairs; per warp, the NEXT pair's 8 KB is
// cp.async-prefetched into a swizzled smem landing buffer while the current
// pair computes -> DRAM stays busy through the compute phase.
// Compute body: R10 plain-rotation f32x2 butterflies (2 rows in the 2 lanes).
// ---------------------------------------------------------------------------
__global__ __launch_bounds__(32 * WPB)
void qnet_kernel(const float* __restrict__ x, float* __restrict__ out,
                 int nrows, int npairs) {
    extern __shared__ __align__(16) char dsm[];
    u64* scratch_all = (u64*)dsm;                         // WPB * 1056 u64
    char* land_all   = dsm + WPB * 8448;                  // WPB * 8192 B
    u64* scoef       = (u64*)(dsm + WPB * 8448 + WPB * 8192);        // 960 B
    unsigned short* sperm = (unsigned short*)((char*)scoef + NL * NQ * 3 * 8);

    int tid = threadIdx.x;
    int2 hdr = *(const int2*)&g_blob.npasses;             // {npasses, ident}
    int np = hdr.x;
    bool fused = (np == 1) && hdr.y;

    for (int i = tid; i < NL * NQ * 3; i += blockDim.x)
        scoef[i] = ((const u64*)g_blob.g)[i];
    if (!fused) {
        for (int i = tid; i < DIM; i += blockDim.x)
            sperm[SWP(i)] = (unsigned short)SWP(g_perm[i]);
    }
    __syncthreads();

    int warp = tid >> 5, lane = tid & 31;
    u64* wb = scratch_all + warp * (DIM + DIM / 32);
    unsigned land = (unsigned)__cvta_generic_to_shared(land_all + warp * 8192);

    int gw = blockIdx.x * WPB + warp;
    int nw = gridDim.x * WPB;

    u64 r[32];

    if (fused) {
        if (gw < npairs) issue_pair_copy(x, gw * 2, nrows, land, lane);

        for (int pair = gw; pair < npairs; pair += nw) {
            int row0 = pair * 2;
            int row1 = (row0 + 1 < nrows) ? row0 + 1 : row0;

            // ---- consume landed pair: LDS.128 x16, pack {row0,row1} ----
            asm volatile("cp.async.wait_group 0;" ::: "memory");
            __syncwarp();
            #pragma unroll
            for (int j = 0; j < 8; j++) {
                int cs = lane * 8 + (j ^ (lane & 7));
                const float4* a0 = (const float4*)(land_all + warp * 8192 + cs * 16);
                const float4* a1 = (const float4*)(land_all + warp * 8192 + 4096 + cs * 16);
                float4 v0 = *a0, v1 = *a1;
                r[j * 4 + 0] = pk2(v0.x, v1.x);
                r[j * 4 + 1] = pk2(v0.y, v1.y);
                r[j * 4 + 2] = pk2(v0.z, v1.z);
                r[j * 4 + 3] = pk2(v0.w, v1.w);
            }
            __syncwarp();

            // ---- prefetch next pair (overlaps all compute below) ----
            int nxt = pair + nw;
            if (nxt < npairs) issue_pair_copy(x, nxt * 2, nrows, land, lane);

            // ---- bits 0..4 (intra-thread, layout A) ----
            #pragma unroll
            for (int b = 0; b < 5; b++) {
                const u64* gg = scoef + (0 * NQ + b) * 3;
                u64 gC = lds64v(gg + 0), gS = lds64v(gg + 1), gN = lds64v(gg + 2);
                int m = 1 << b;
                #pragma unroll
                for (int k0 = 0; k0 < 32; k0++) {
                    if (k0 & m) continue;
                    int k1 = k0 | m;
                    u64 x0 = r[k0], x1 = r[k1];
                    r[k0] = fma2(gC, x0, mul2(gN, x1));
                    r[k1] = fma2(gS, x0, mul2(gC, x1));
                }
            }

            // ---- transpose A -> B (conflict-free both directions) ----
            __syncwarp();
            #pragma unroll
            for (int k = 0; k < 32; k++) wb[SWP(lane * 32 + k)] = r[k];
            __syncwarp();
            #pragma unroll
            for (int k = 0; k < 32; k++) r[k] = wb[SWP(k * 32 + lane)];

            // ---- bits 5..9 (intra-thread, layout B) ----
            #pragma unroll
            for (int b = 5; b < 10; b++) {
                const u64* gg = scoef + (0 * NQ + b) * 3;
                u64 gC = lds64v(gg + 0), gS = lds64v(gg + 1), gN = lds64v(gg + 2);
                int m = 1 << (b - 5);
                #pragma unroll
                for (int k0 = 0; k0 < 32; k0++) {
                    if (k0 & m) continue;
                    int k1 = k0 | m;
                    u64 x0 = r[k0], x1 = r[k1];
                    r[k0] = fma2(gC, x0, mul2(gN, x1));
                    r[k1] = fma2(gS, x0, mul2(gC, x1));
                }
            }

            // ---- store layout B: element i = k*32+lane, coalesced STG.32 ----
            float* o0 = out + (size_t)row0 * DIM + lane;
            float* o1 = out + (size_t)row1 * DIM + lane;
            #pragma unroll
            for (int k = 0; k < 32; k++) {
                float lo, hi; unpk2(r[k], lo, hi);
                o0[k * 32] = lo;
                o1[k * 32] = hi;
            }
        }
        return;
    }

    // =================== general path (multi-pass, permutation) ===========
    for (int pair = gw; pair < npairs; pair += nw) {
        int row0 = pair * 2;
        int row1 = (row0 + 1 < nrows) ? row0 + 1 : row0;

        const float4* p0 = (const float4*)(x + (size_t)row0 * DIM + lane * 32);
        const float4* p1 = (const float4*)(x + (size_t)row1 * DIM + lane * 32);
        #pragma unroll
        for (int k4 = 0; k4 < 8; k4++) {
            float4 v0 = p0[k4], v1 = p1[k4];
            r[k4 * 4 + 0] = pk2(v0.x, v1.x);
            r[k4 * 4 + 1] = pk2(v0.y, v1.y);
            r[k4 * 4 + 2] = pk2(v0.z, v1.z);
            r[k4 * 4 + 3] = pk2(v0.w, v1.w);
        }

        for (int p = 0; p < np; p++) {
            #pragma unroll
            for (int b = 0; b < 5; b++) {
                const u64* gg = scoef + (p * NQ + b) * 3;
                u64 gC = lds64v(gg + 0), gS = lds64v(gg + 1), gN = lds64v(gg + 2);
                int m = 1 << b;
                #pragma unroll
                for (int k0 = 0; k0 < 32; k0++) {
                    if (k0 & m) continue;
                    int k1 = k0 | m;
                    u64 x0 = r[k0], x1 = r[k1];
                    r[k0] = fma2(gC, x0, mul2(gN, x1));
                    r[k1] = fma2(gS, x0, mul2(gC, x1));
                }
            }

            __syncwarp();
            #pragma unroll
            for (int k = 0; k < 32; k++) wb[SWP(lane * 32 + k)] = r[k];
            __syncwarp();
            #pragma unroll
            for (int k = 0; k < 32; k++) r[k] = wb[SWP(k * 32 + lane)];

            #pragma unroll
            for (int b = 5; b < 10; b++) {
                const u64* gg = scoef + (p * NQ + b) * 3;
                u64 gC = lds64v(gg + 0), gS = lds64v(gg + 1), gN = lds64v(gg + 2);
                int m = 1 << (b - 5);
                #pragma unroll
                for (int k0 = 0; k0 < 32; k0++) {
                    if (k0 & m) continue;
                    int k1 = k0 | m;
                    u64 x0 = r[k0], x1 = r[k1];
                    r[k0] = fma2(gC, x0, mul2(gN, x1));
                    r[k1] = fma2(gS, x0, mul2(gC, x1));
                }
            }

            __syncwarp();
            #pragma unroll
            for (int k = 0; k < 32; k++) wb[SWP(k * 32 + lane)] = r[k];
            __syncwarp();
            #pragma unroll
            for (int k = 0; k < 32; k++) r[k] = wb[sperm[SWP(lane * 32 + k)]];
        }

        float4* o0 = (float4*)(out + (size_t)row0 * DIM + lane * 32);
        float4* o1 = (float4*)(out + (size_t)row1 * DIM + lane * 32);
        #pragma unroll
        for (int k4 = 0; k4 < 8; k4++) {
            float4 v0, v1;
            unpk2(r[k4 * 4 + 0], v0.x, v1.x);
            unpk2(r[k4 * 4 + 1], v0.y, v1.y);
            unpk2(r[k4 * 4 + 2], v0.z, v1.z);
            unpk2(r[k4 * 4 + 3], v0.w, v1.w);
            o0[k4] = v0; o1[k4] = v1;
        }
    }
}

// ---------------------------------------------------------------------------
extern "C" void kernel_launch(void* const* d_in, const int* in_sizes, int n_in,
                              void* d_out, int out_size) {
    const float* x      = (const float*)d_in[0];   // [BATCH, 1024]
    const float* angles = (const float*)d_in[1];   // [4, 10, 3]
    const float* cnot   = (const float*)d_in[2];   // [1024, 1024]
    float* out = (float*)d_out;

    int nrows  = in_sizes[0] / DIM;
    int npairs = (nrows + 1) / 2;

    prep_kernel<<<1, DIM>>>(cnot, angles);

    // dynamic smem: WPB*(8448 scratch + 8192 landing) + coeffs + sperm
    int smem = WPB * 8448 + WPB * 8192 + NL * NQ * 3 * 8 + (DIM + DIM / 32) * 2;
    static int attr_set = 0;
    cudaFuncSetAttribute(qnet_kernel,
                         cudaFuncAttributeMaxDynamicSharedMemorySize, smem);
    (void)attr_set;

    int nblocks = (npairs + WPB - 1) / WPB;
    int cap = 148 * 3;                 // ~3 blocks/SM resident (smem-limited)
    if (nblocks > cap) nblocks = cap;
    qnet_kernel<<<nblocks, 32 * WPB, smem>>>(x, out, nrows, npairs);
}

// round 15
// speedup vs baseline: 1.2774x; 1.0755x over previous
#include <cuda_runtime.h>

#define DIM 1024
#define NQ 10
#define NL 4
#define WPB 4                          // warps per block (each warp = 2 rows)
#define SWP(i) ((i) + ((i) >> 5))      // stride-33 swizzle for transpose scratch

typedef unsigned long long u64;

__device__ __forceinline__ u64 pk2(float lo, float hi) {
    u64 r; asm("mov.b64 %0, {%1, %2};" : "=l"(r) : "f"(lo), "f"(hi)); return r;
}
__device__ __forceinline__ void unpk2(u64 v, float& lo, float& hi) {
    asm("mov.b64 {%0, %1}, %2;" : "=f"(lo), "=f"(hi) : "l"(v));
}
__device__ __forceinline__ u64 fma2(u64 a, u64 b, u64 c) {
    u64 d; asm("fma.rn.f32x2 %0, %1, %2, %3;" : "=l"(d) : "l"(a), "l"(b), "l"(c)); return d;
}
__device__ __forceinline__ u64 mul2(u64 a, u64 b) {
    u64 d; asm("mul.rn.f32x2 %0, %1, %2;" : "=l"(d) : "l"(a), "l"(b)); return d;
}
// volatile LDS.64 broadcast: pinned in place (no register hoisting),
// no global memory-clobber -> FMA scheduling around it stays free.
__device__ __forceinline__ u64 lds64v(const u64* p) {
    u64 v;
    asm volatile("ld.shared.b64 %0, [%1];"
                 : "=l"(v) : "r"((unsigned)__cvta_generic_to_shared(p)));
    return v;
}

// 16B-chunk XOR swizzle for the cp.async landing buffer: chunk c of a row
// lands at c ^ ((c>>3)&7). Reader (lane l, chunk j of 8): c' = l*8 + (j^(l&7))
// -> conflict-free LDS.128; writer lanes conflict-free likewise.
__device__ __forceinline__ void issue_pair_copy(
    const float* __restrict__ x, int row0, int nrows, unsigned land, int lane) {
    #pragma unroll
    for (int i = 0; i < 16; i++) {
        int ct = i * 32 + lane;           // 512 chunks of 16 B = 2 rows
        int r  = ct >> 8;
        int c  = ct & 255;
        int cs = c ^ ((c >> 3) & 7);
        int srow = row0 + r;
        if (srow >= nrows) srow = row0;   // odd tail: duplicate row0
        const float* src = x + (size_t)srow * DIM + c * 4;
        unsigned dst = land + r * 4096 + cs * 16;
        asm volatile("cp.async.cg.shared.global [%0], [%1], 16;"
                     :: "r"(dst), "l"(src) : "memory");
    }
    asm volatile("cp.async.commit_group;" ::: "memory");
}

// ---------------------------------------------------------------------------
// SINGLE fused kernel. Each block:
//   1) issues its first cp.async prefetch immediately (starts DRAM),
//   2) inlines "prep" under that fetch: diagonal identity-check of the cnot
//      matrix (L2-hot), per-bit rotation angles (gate = rotation by
//      (a0+a1+a2)/2; layer composition = angle sum when perm == identity),
//      coefficients straight into smem; general path builds sperm in-block,
//   3) runs the R14 grid-stride pipelined butterfly loop (unchanged).
// ---------------------------------------------------------------------------
__global__ __launch_bounds__(32 * WPB)
void qnet_kernel(const float* __restrict__ x, float* __restrict__ out,
                 const float* __restrict__ angles,
                 const float* __restrict__ cnot,
                 int nrows, int npairs) {
    extern __shared__ __align__(16) char dsm[];
    u64*  scratch_all = (u64*)dsm;                            // WPB*1056 u64
    char* land_all    = dsm + WPB * 8448;                     // WPB*8192 B
    u64*  scoef       = (u64*)(dsm + WPB * 8448 + WPB * 8192);      // 960 B
    unsigned short* sperm = (unsigned short*)((char*)scoef + NL * NQ * 3 * 8);
    float* sTH   = (float*)((char*)sperm + (DIM + DIM / 32) * 2);   // 40 floats
    int*   sflag = (int*)(sTH + NL * NQ);

    int tid  = threadIdx.x;
    int warp = tid >> 5, lane = tid & 31;
    u64* wb = scratch_all + warp * (DIM + DIM / 32);
    unsigned land = (unsigned)__cvta_generic_to_shared(land_all + warp * 8192);

    int gw = blockIdx.x * WPB + warp;
    int nw = gridDim.x * WPB;

    // ---- 1) kick off the first prefetch before anything else ----
    if (gw < npairs) issue_pair_copy(x, gw * 2, nrows, land, lane);

    // ---- 2) inline prep (hidden under the prefetch's DRAM latency) ----
    if (tid == 0) *sflag = 1;
    __syncthreads();
    {
        int bad = 0;
        for (int i = tid; i < DIM; i += blockDim.x)
            if (cnot[(size_t)i * DIM + i] == 0.0f) bad = 1;
        if (bad) atomicExch(sflag, 0);
    }
    if (tid < NL * NQ) {   // gate (l,q) = rotation by (a0+a1+a2)/2; bit b = 9-q
        int l = tid / NQ, q = tid % NQ, b = 9 - q;
        const float* a = angles + (size_t)(l * NQ + q) * 3;
        sTH[l * NQ + b] = 0.5f * (a[0] + a[1] + a[2]);
    }
    __syncthreads();

    bool fused = (*sflag != 0);
    if (fused) {
        if (tid < NQ) {    // compose all layers per bit: angle sum
            float th = 0.f;
            #pragma unroll
            for (int l = 0; l < NL; l++) th += sTH[l * NQ + tid];
            float c = cosf(th), s = sinf(th);
            scoef[tid * 3 + 0] = pk2(c, c);
            scoef[tid * 3 + 1] = pk2(s, s);
            scoef[tid * 3 + 2] = pk2(-s, -s);
        }
    } else {
        if (tid < NL * NQ) {
            float th = sTH[tid];
            float c = cosf(th), s = sinf(th);
            scoef[tid * 3 + 0] = pk2(c, c);
            scoef[tid * 3 + 1] = pk2(s, s);
            scoef[tid * 3 + 2] = pk2(-s, -s);
        }
        // perm: row i -> first nonzero column (diag shortcut avoids row scan)
        for (int i = tid; i < DIM; i += blockDim.x) {
            int p = i;
            if (cnot[(size_t)i * DIM + i] == 0.0f) {
                const float* row = cnot + (size_t)i * DIM;
                for (int j = 0; j < DIM; j++)
                    if (row[j] != 0.0f) { p = j; break; }
            }
            sperm[SWP(i)] = (unsigned short)SWP(p);
        }
    }
    __syncthreads();

    u64 r[32];

    if (fused) {
        for (int pair = gw; pair < npairs; pair += nw) {
            int row0 = pair * 2;
            int row1 = (row0 + 1 < nrows) ? row0 + 1 : row0;

            // ---- consume landed pair: LDS.128 x16, pack {row0,row1} ----
            asm volatile("cp.async.wait_group 0;" ::: "memory");
            __syncwarp();
            #pragma unroll
            for (int j = 0; j < 8; j++) {
                int cs = lane * 8 + (j ^ (lane & 7));
                const float4* a0 = (const float4*)(land_all + warp * 8192 + cs * 16);
                const float4* a1 = (const float4*)(land_all + warp * 8192 + 4096 + cs * 16);
                float4 v0 = *a0, v1 = *a1;
                r[j * 4 + 0] = pk2(v0.x, v1.x);
                r[j * 4 + 1] = pk2(v0.y, v1.y);
                r[j * 4 + 2] = pk2(v0.z, v1.z);
                r[j * 4 + 3] = pk2(v0.w, v1.w);
            }
            __syncwarp();

            // ---- prefetch next pair (overlaps all compute below) ----
            int nxt = pair + nw;
            if (nxt < npairs) issue_pair_copy(x, nxt * 2, nrows, land, lane);

            // ---- bits 0..4 (intra-thread, layout A) ----
            #pragma unroll
            for (int b = 0; b < 5; b++) {
                const u64* gg = scoef + b * 3;
                u64 gC = lds64v(gg + 0), gS = lds64v(gg + 1), gN = lds64v(gg + 2);
                int m = 1 << b;
                #pragma unroll
                for (int k0 = 0; k0 < 32; k0++) {
                    if (k0 & m) continue;
                    int k1 = k0 | m;
                    u64 x0 = r[k0], x1 = r[k1];
                    r[k0] = fma2(gC, x0, mul2(gN, x1));
                    r[k1] = fma2(gS, x0, mul2(gC, x1));
                }
            }

            // ---- transpose A -> B (conflict-free both directions) ----
            __syncwarp();
            #pragma unroll
            for (int k = 0; k < 32; k++) wb[SWP(lane * 32 + k)] = r[k];
            __syncwarp();
            #pragma unroll
            for (int k = 0; k < 32; k++) r[k] = wb[SWP(k * 32 + lane)];

            // ---- bits 5..9 (intra-thread, layout B) ----
            #pragma unroll
            for (int b = 5; b < 10; b++) {
                const u64* gg = scoef + b * 3;
                u64 gC = lds64v(gg + 0), gS = lds64v(gg + 1), gN = lds64v(gg + 2);
                int m = 1 << (b - 5);
                #pragma unroll
                for (int k0 = 0; k0 < 32; k0++) {
                    if (k0 & m) continue;
                    int k1 = k0 | m;
                    u64 x0 = r[k0], x1 = r[k1];
                    r[k0] = fma2(gC, x0, mul2(gN, x1));
                    r[k1] = fma2(gS, x0, mul2(gC, x1));
                }
            }

            // ---- store layout B: element i = k*32+lane, coalesced STG.32 ----
            float* o0 = out + (size_t)row0 * DIM + lane;
            float* o1 = out + (size_t)row1 * DIM + lane;
            #pragma unroll
            for (int k = 0; k < 32; k++) {
                float lo, hi; unpk2(r[k], lo, hi);
                o0[k * 32] = lo;
                o1[k * 32] = hi;
            }
        }
        return;
    }

    // =================== general path (multi-pass, permutation) ===========
    for (int pair = gw; pair < npairs; pair += nw) {
        int row0 = pair * 2;
        int row1 = (row0 + 1 < nrows) ? row0 + 1 : row0;

        const float4* p0 = (const float4*)(x + (size_t)row0 * DIM + lane * 32);
        const float4* p1 = (const float4*)(x + (size_t)row1 * DIM + lane * 32);
        #pragma unroll
        for (int k4 = 0; k4 < 8; k4++) {
            float4 v0 = p0[k4], v1 = p1[k4];
            r[k4 * 4 + 0] = pk2(v0.x, v1.x);
            r[k4 * 4 + 1] = pk2(v0.y, v1.y);
            r[k4 * 4 + 2] = pk2(v0.z, v1.z);
            r[k4 * 4 + 3] = pk2(v0.w, v1.w);
        }

        for (int p = 0; p < NL; p++) {
            #pragma unroll
            for (int b = 0; b < 5; b++) {
                const u64* gg = scoef + (p * NQ + b) * 3;
                u64 gC = lds64v(gg + 0), gS = lds64v(gg + 1), gN = lds64v(gg + 2);
                int m = 1 << b;
                #pragma unroll
                for (int k0 = 0; k0 < 32; k0++) {
                    if (k0 & m) continue;
                    int k1 = k0 | m;
                    u64 x0 = r[k0], x1 = r[k1];
                    r[k0] = fma2(gC, x0, mul2(gN, x1));
                    r[k1] = fma2(gS, x0, mul2(gC, x1));
                }
            }

            __syncwarp();
            #pragma unroll
            for (int k = 0; k < 32; k++) wb[SWP(lane * 32 + k)] = r[k];
            __syncwarp();
            #pragma unroll
            for (int k = 0; k < 32; k++) r[k] = wb[SWP(k * 32 + lane)];

            #pragma unroll
            for (int b = 5; b < 10; b++) {
                const u64* gg = scoef + (p * NQ + b) * 3;
                u64 gC = lds64v(gg + 0), gS = lds64v(gg + 1), gN = lds64v(gg + 2);
                int m = 1 << (b - 5);
                #pragma unroll
                for (int k0 = 0; k0 < 32; k0++) {
                    if (k0 & m) continue;
                    int k1 = k0 | m;
                    u64 x0 = r[k0], x1 = r[k1];
                    r[k0] = fma2(gC, x0, mul2(gN, x1));
                    r[k1] = fma2(gS, x0, mul2(gC, x1));
                }
            }

            __syncwarp();
            #pragma unroll
            for (int k = 0; k < 32; k++) wb[SWP(k * 32 + lane)] = r[k];
            __syncwarp();
            #pragma unroll
            for (int k = 0; k < 32; k++) r[k] = wb[sperm[SWP(lane * 32 + k)]];
        }

        float4* o0 = (float4*)(out + (size_t)row0 * DIM + lane * 32);
        float4* o1 = (float4*)(out + (size_t)row1 * DIM + lane * 32);
        #pragma unroll
        for (int k4 = 0; k4 < 8; k4++) {
            float4 v0, v1;
            unpk2(r[k4 * 4 + 0], v0.x, v1.x);
            unpk2(r[k4 * 4 + 1], v0.y, v1.y);
            unpk2(r[k4 * 4 + 2], v0.z, v1.z);
            unpk2(r[k4 * 4 + 3], v0.w, v1.w);
            o0[k4] = v0; o1[k4] = v1;
        }
    }
}

// ---------------------------------------------------------------------------
extern "C" void kernel_launch(void* const* d_in, const int* in_sizes, int n_in,
                              void* d_out, int out_size) {
    const float* x      = (const float*)d_in[0];   // [BATCH, 1024]
    const float* angles = (const float*)d_in[1];   // [4, 10, 3]
    const float* cnot   = (const float*)d_in[2];   // [1024, 1024]
    float* out = (float*)d_out;

    int nrows  = in_sizes[0] / DIM;
    int npairs = (nrows + 1) / 2;

    // dynamic smem: scratch + landing + coeffs + sperm + angles + flag
    int smem = WPB * 8448 + WPB * 8192 + NL * NQ * 3 * 8
             + (DIM + DIM / 32) * 2 + NL * NQ * 4 + 16;
    cudaFuncSetAttribute(qnet_kernel,
                         cudaFuncAttributeMaxDynamicSharedMemorySize, smem);

    int nblocks = (npairs + WPB - 1) / WPB;
    int cap = 148 * 3;                 // 3 blocks/SM resident (smem-limited)
    if (nblocks > cap) nblocks = cap;
    qnet_kernel<<<nblocks, 32 * WPB, smem>>>(x, out, angles, cnot, nrows, npairs);
}

// round 16
// speedup vs baseline: 1.2870x; 1.0075x over previous
#include <cuda_runtime.h>

#define DIM 1024
#define NQ 10
#define NL 4
#define WPB 4                          // warps per block (each warp = 2 rows)
#define WBUF 8448                      // per-warp buffer: landing (8192) / transpose (8448)
#define SWP(i) ((i) + ((i) >> 5))      // stride-33 swizzle for transpose layout

typedef unsigned long long u64;

__device__ __forceinline__ u64 pk2(float lo, float hi) {
    u64 r; asm("mov.b64 %0, {%1, %2};" : "=l"(r) : "f"(lo), "f"(hi)); return r;
}
__device__ __forceinline__ void unpk2(u64 v, float& lo, float& hi) {
    asm("mov.b64 {%0, %1}, %2;" : "=f"(lo), "=f"(hi) : "l"(v));
}
__device__ __forceinline__ u64 fma2(u64 a, u64 b, u64 c) {
    u64 d; asm("fma.rn.f32x2 %0, %1, %2, %3;" : "=l"(d) : "l"(a), "l"(b), "l"(c)); return d;
}
__device__ __forceinline__ u64 mul2(u64 a, u64 b) {
    u64 d; asm("mul.rn.f32x2 %0, %1, %2;" : "=l"(d) : "l"(a), "l"(b)); return d;
}
// volatile LDS.64 broadcast: pinned in place (no register hoisting),
// no global memory-clobber -> FMA scheduling around it stays free.
__device__ __forceinline__ u64 lds64v(const u64* p) {
    u64 v;
    asm volatile("ld.shared.b64 %0, [%1];"
                 : "=l"(v) : "r"((unsigned)__cvta_generic_to_shared(p)));
    return v;
}

// 16B-chunk XOR swizzle for the cp.async landing layout: chunk c of a row
// lands at c ^ ((c>>3)&7). Reader (lane l, chunk j of 8): c' = l*8 + (j^(l&7))
// -> conflict-free LDS.128; writer lanes conflict-free likewise.
__device__ __forceinline__ void issue_pair_copy(
    const float* __restrict__ x, int row0, int nrows, unsigned land, int lane) {
    #pragma unroll
    for (int i = 0; i < 16; i++) {
        int ct = i * 32 + lane;           // 512 chunks of 16 B = 2 rows
        int rr = ct >> 8;
        int c  = ct & 255;
        int cs = c ^ ((c >> 3) & 7);
        int srow = row0 + rr;
        if (srow >= nrows) srow = row0;   // odd tail: duplicate row0
        const float* src = x + (size_t)srow * DIM + c * 4;
        unsigned dst = land + rr * 4096 + cs * 16;
        asm volatile("cp.async.cg.shared.global [%0], [%1], 16;"
                     :: "r"(dst), "l"(src) : "memory");
    }
}
#define COMMIT() asm volatile("cp.async.commit_group;" ::: "memory")

// ---------------------------------------------------------------------------
// SINGLE fused kernel, depth-2 ping-pong input pipeline.
// Per warp: two 8448 B buffers. Buffer serving pair n: cp.async landing ->
// consumed to registers -> reused as transpose scratch for pair n ->
// immediately refilled (cp.async) with pair n+2. Commit accounting:
// 2 prologue commits + 1 unconditional commit per iteration => wait_group 1
// at iteration top completes exactly the needed group.
// ---------------------------------------------------------------------------
__global__ __launch_bounds__(32 * WPB)
void qnet_kernel(const float* __restrict__ x, float* __restrict__ out,
                 const float* __restrict__ angles,
                 const float* __restrict__ cnot,
                 int nrows, int npairs) {
    extern __shared__ __align__(16) char dsm[];
    char* wbase = dsm;                                        // WPB*2*WBUF
    u64*  scoef = (u64*)(dsm + WPB * 2 * WBUF);               // 960 B
    unsigned short* sperm = (unsigned short*)((char*)scoef + NL * NQ * 3 * 8);
    float* sTH   = (float*)((char*)sperm + (DIM + DIM / 32) * 2);   // 40 floats
    int*   sflag = (int*)(sTH + NL * NQ);

    int tid  = threadIdx.x;
    int warp = tid >> 5, lane = tid & 31;
    char* wbuf0 = wbase + warp * (2 * WBUF);
    char* wbuf1 = wbuf0 + WBUF;
    unsigned land0 = (unsigned)__cvta_generic_to_shared(wbuf0);
    unsigned land1 = (unsigned)__cvta_generic_to_shared(wbuf1);

    int gw = blockIdx.x * WPB + warp;
    int nw = gridDim.x * WPB;

    // ---- prologue: two prefetches in flight before anything else ----
    if (gw < npairs) issue_pair_copy(x, gw * 2, nrows, land0, lane);
    COMMIT();
    if (gw + nw < npairs) issue_pair_copy(x, (gw + nw) * 2, nrows, land1, lane);
    COMMIT();

    // ---- inline prep (hidden under the prefetches' DRAM latency) ----
    if (tid == 0) *sflag = 1;
    __syncthreads();
    {
        int bad = 0;
        for (int i = tid; i < DIM; i += blockDim.x)
            if (cnot[(size_t)i * DIM + i] == 0.0f) bad = 1;
        if (bad) atomicExch(sflag, 0);
    }
    if (tid < NL * NQ) {   // gate (l,q) = rotation by (a0+a1+a2)/2; bit b = 9-q
        int l = tid / NQ, q = tid % NQ, b = 9 - q;
        const float* a = angles + (size_t)(l * NQ + q) * 3;
        sTH[l * NQ + b] = 0.5f * (a[0] + a[1] + a[2]);
    }
    __syncthreads();

    bool fused = (*sflag != 0);
    if (fused) {
        if (tid < NQ) {    // compose all layers per bit: angle sum
            float th = 0.f;
            #pragma unroll
            for (int l = 0; l < NL; l++) th += sTH[l * NQ + tid];
            float c = cosf(th), s = sinf(th);
            scoef[tid * 3 + 0] = pk2(c, c);
            scoef[tid * 3 + 1] = pk2(s, s);
            scoef[tid * 3 + 2] = pk2(-s, -s);
        }
    } else {
        if (tid < NL * NQ) {
            float th = sTH[tid];
            float c = cosf(th), s = sinf(th);
            scoef[tid * 3 + 0] = pk2(c, c);
            scoef[tid * 3 + 1] = pk2(s, s);
            scoef[tid * 3 + 2] = pk2(-s, -s);
        }
        // perm: row i -> first nonzero column (diag shortcut avoids row scan)
        for (int i = tid; i < DIM; i += blockDim.x) {
            int p = i;
            if (cnot[(size_t)i * DIM + i] == 0.0f) {
                const float* row = cnot + (size_t)i * DIM;
                for (int j = 0; j < DIM; j++)
                    if (row[j] != 0.0f) { p = j; break; }
            }
            sperm[SWP(i)] = (unsigned short)SWP(p);
        }
    }
    __syncthreads();

    u64 r[32];

    if (fused) {
        int it = 0;
        for (int pair = gw; pair < npairs; pair += nw, ++it) {
            char* cur = (it & 1) ? wbuf1 : wbuf0;
            unsigned landc = (it & 1) ? land1 : land0;
            int row0 = pair * 2;
            int row1 = (row0 + 1 < nrows) ? row0 + 1 : row0;

            // ---- wait for this pair's landing (1 younger group allowed) ----
            asm volatile("cp.async.wait_group 1;" ::: "memory");
            __syncwarp();
            #pragma unroll
            for (int j = 0; j < 8; j++) {
                int cs = lane * 8 + (j ^ (lane & 7));
                float4 v0 = *(const float4*)(cur + cs * 16);
                float4 v1 = *(const float4*)(cur + 4096 + cs * 16);
                r[j * 4 + 0] = pk2(v0.x, v1.x);
                r[j * 4 + 1] = pk2(v0.y, v1.y);
                r[j * 4 + 2] = pk2(v0.z, v1.z);
                r[j * 4 + 3] = pk2(v0.w, v1.w);
            }

            // ---- bits 0..4 (intra-thread, layout A) ----
            #pragma unroll
            for (int b = 0; b < 5; b++) {
                const u64* gg = scoef + b * 3;
                u64 gC = lds64v(gg + 0), gS = lds64v(gg + 1), gN = lds64v(gg + 2);
                int m = 1 << b;
                #pragma unroll
                for (int k0 = 0; k0 < 32; k0++) {
                    if (k0 & m) continue;
                    int k1 = k0 | m;
                    u64 x0 = r[k0], x1 = r[k1];
                    r[k0] = fma2(gC, x0, mul2(gN, x1));
                    r[k1] = fma2(gS, x0, mul2(gC, x1));
                }
            }

            // ---- transpose A -> B in the just-consumed buffer ----
            u64* wb = (u64*)cur;
            __syncwarp();
            #pragma unroll
            for (int k = 0; k < 32; k++) wb[SWP(lane * 32 + k)] = r[k];
            __syncwarp();
            #pragma unroll
            for (int k = 0; k < 32; k++) r[k] = wb[SWP(k * 32 + lane)];
            __syncwarp();

            // ---- buffer now free: prefetch pair + 2*nw into it ----
            int nxt = pair + 2 * nw;
            if (nxt < npairs) issue_pair_copy(x, nxt * 2, nrows, landc, lane);
            COMMIT();   // unconditional: keeps group counting aligned

            // ---- bits 5..9 (intra-thread, layout B) ----
            #pragma unroll
            for (int b = 5; b < 10; b++) {
                const u64* gg = scoef + b * 3;
                u64 gC = lds64v(gg + 0), gS = lds64v(gg + 1), gN = lds64v(gg + 2);
                int m = 1 << (b - 5);
                #pragma unroll
                for (int k0 = 0; k0 < 32; k0++) {
                    if (k0 & m) continue;
                    int k1 = k0 | m;
                    u64 x0 = r[k0], x1 = r[k1];
                    r[k0] = fma2(gC, x0, mul2(gN, x1));
                    r[k1] = fma2(gS, x0, mul2(gC, x1));
                }
            }

            // ---- store layout B: element i = k*32+lane, coalesced STG.32 ----
            float* o0 = out + (size_t)row0 * DIM + lane;
            float* o1 = out + (size_t)row1 * DIM + lane;
            #pragma unroll
            for (int k = 0; k < 32; k++) {
                float lo, hi; unpk2(r[k], lo, hi);
                o0[k * 32] = lo;
                o1[k * 32] = hi;
            }
        }
        asm volatile("cp.async.wait_group 0;" ::: "memory");   // drain
        return;
    }

    // =================== general path (multi-pass, permutation) ===========
    asm volatile("cp.async.wait_group 0;" ::: "memory");       // discard prologue
    __syncwarp();
    u64* wb = (u64*)wbuf0;
    for (int pair = gw; pair < npairs; pair += nw) {
        int row0 = pair * 2;
        int row1 = (row0 + 1 < nrows) ? row0 + 1 : row0;

        const float4* p0 = (const float4*)(x + (size_t)row0 * DIM + lane * 32);
        const float4* p1 = (const float4*)(x + (size_t)row1 * DIM + lane * 32);
        #pragma unroll
        for (int k4 = 0; k4 < 8; k4++) {
            float4 v0 = p0[k4], v1 = p1[k4];
            r[k4 * 4 + 0] = pk2(v0.x, v1.x);
            r[k4 * 4 + 1] = pk2(v0.y, v1.y);
            r[k4 * 4 + 2] = pk2(v0.z, v1.z);
            r[k4 * 4 + 3] = pk2(v0.w, v1.w);
        }

        for (int p = 0; p < NL; p++) {
            #pragma unroll
            for (int b = 0; b < 5; b++) {
                const u64* gg = scoef + (p * NQ + b) * 3;
                u64 gC = lds64v(gg + 0), gS = lds64v(gg + 1), gN = lds64v(gg + 2);
                int m = 1 << b;
                #pragma unroll
                for (int k0 = 0; k0 < 32; k0++) {
                    if (k0 & m) continue;
                    int k1 = k0 | m;
                    u64 x0 = r[k0], x1 = r[k1];
                    r[k0] = fma2(gC, x0, mul2(gN, x1));
                    r[k1] = fma2(gS, x0, mul2(gC, x1));
                }
            }

            __syncwarp();
            #pragma unroll
            for (int k = 0; k < 32; k++) wb[SWP(lane * 32 + k)] = r[k];
            __syncwarp();
            #pragma unroll
            for (int k = 0; k < 32; k++) r[k] = wb[SWP(k * 32 + lane)];

            #pragma unroll
            for (int b = 5; b < 10; b++) {
                const u64* gg = scoef + (p * NQ + b) * 3;
                u64 gC = lds64v(gg + 0), gS = lds64v(gg + 1), gN = lds64v(gg + 2);
                int m = 1 << (b - 5);
                #pragma unroll
                for (int k0 = 0; k0 < 32; k0++) {
                    if (k0 & m) continue;
                    int k1 = k0 | m;
                    u64 x0 = r[k0], x1 = r[k1];
                    r[k0] = fma2(gC, x0, mul2(gN, x1));
                    r[k1] = fma2(gS, x0, mul2(gC, x1));
                }
            }

            __syncwarp();
            #pragma unroll
            for (int k = 0; k < 32; k++) wb[SWP(k * 32 + lane)] = r[k];
            __syncwarp();
            #pragma unroll
            for (int k = 0; k < 32; k++) r[k] = wb[sperm[SWP(lane * 32 + k)]];
        }

        float4* o0 = (float4*)(out + (size_t)row0 * DIM + lane * 32);
        float4* o1 = (float4*)(out + (size_t)row1 * DIM + lane * 32);
        #pragma unroll
        for (int k4 = 0; k4 < 8; k4++) {
            float4 v0, v1;
            unpk2(r[k4 * 4 + 0], v0.x, v1.x);
            unpk2(r[k4 * 4 + 1], v0.y, v1.y);
            unpk2(r[k4 * 4 + 2], v0.z, v1.z);
            unpk2(r[k4 * 4 + 3], v0.w, v1.w);
            o0[k4] = v0; o1[k4] = v1;
        }
    }
}

// ---------------------------------------------------------------------------
extern "C" void kernel_launch(void* const* d_in, const int* in_sizes, int n_in,
                              void* d_out, int out_size) {
    const float* x      = (const float*)d_in[0];   // [BATCH, 1024]
    const float* angles = (const float*)d_in[1];   // [4, 10, 3]
    const float* cnot   = (const float*)d_in[2];   // [1024, 1024]
    float* out = (float*)d_out;

    int nrows  = in_sizes[0] / DIM;
    int npairs = (nrows + 1) / 2;

    // dynamic smem: ping-pong buffers + coeffs + sperm + angles + flag
    int smem = WPB * 2 * WBUF + NL * NQ * 3 * 8
             + (DIM + DIM / 32) * 2 + NL * NQ * 4 + 16;
    cudaFuncSetAttribute(qnet_kernel,
                         cudaFuncAttributeMaxDynamicSharedMemorySize, smem);

    int nblocks = (npairs + WPB - 1) / WPB;
    int cap = 148 * 3;                 // 3 blocks/SM resident (smem-limited)
    if (nblocks > cap) nblocks = cap;
    qnet_kernel<<<nblocks, 32 * WPB, smem>>>(x, out, angles, cnot, nrows, npairs);
}